// round 16
// baseline (speedup 1.0000x reference)
#include <cuda_runtime.h>

// out[t,b,i,e] = x[t,b,i] * W[i,e] + b[e]
// T=8, B=64, D=512, E=256. k = t*B+b in [0,512).
// out4[(k*512 + i)*64 + e4] = x[k*512 + i] * W4[i*64 + e4] + b4[e4]
//
// R15: quasi-persistent variant of the plateau kernel (R5/R13, 41.44us wall).
// Grid (512, 2) = 1024 blocks; each block processes 4 k-chunks of 64
// sequentially, W/b hoisted across all 4 (cuts wave transitions ~4x and W
// reload traffic 4x). Inner pattern byte-identical: 16 batched uniform
// x-loads, 16 back-to-back FMA4 + __stcs STG.128.

#define D_DIM 512
#define E4    64
#define KK 16
#define CHUNKS_PER_BLK 4
#define GRID_Y 2            // 2 * 4 chunks * 64 k = 512 k total

__global__ __launch_bounds__(256) void dense_embed_kernel(
    const float* __restrict__ x,    // [512 * 512]
    const float4* __restrict__ W4,  // [512 * 64]
    const float4* __restrict__ b4,  // [64]
    float4* __restrict__ out4)      // [512 * 512 * 64]
{
    const unsigned i  = blockIdx.x;               // 0..511
    const unsigned e4 = threadIdx.x & (E4 - 1);   // 0..63
    const unsigned kg = threadIdx.x >> 6;         // 0..3

    // Per-thread invariants, hoisted across all 4 chunks.
    const float4 w  = __ldg(&W4[i * E4 + e4]);
    const float4 bb = __ldg(&b4[e4]);

    #pragma unroll
    for (int c = 0; c < CHUNKS_PER_BLK; ++c) {
        const unsigned k0 = blockIdx.y * (CHUNKS_PER_BLK * 64) + c * 64 + kg * KK;

        const float* xp = x + (size_t)k0 * D_DIM + i;
        float4* op = out4 + ((size_t)k0 * D_DIM + i) * E4 + e4;

        // Batch all 16 x loads up front — independent, fully overlapped.
        float xv[KK];
        #pragma unroll
        for (int kk = 0; kk < KK; kk++)
            xv[kk] = __ldg(&xp[(size_t)kk * D_DIM]);

        // Pure store stream: 16 back-to-back FMA4 + evict-first STG.128.
        #pragma unroll
        for (int kk = 0; kk < KK; kk++) {
            float4 o;
            o.x = fmaf(xv[kk], w.x, bb.x);
            o.y = fmaf(xv[kk], w.y, bb.y);
            o.z = fmaf(xv[kk], w.z, bb.z);
            o.w = fmaf(xv[kk], w.w, bb.w);
            __stcs(&op[(size_t)kk * D_DIM * E4], o);
        }
    }
}

extern "C" void kernel_launch(void* const* d_in, const int* in_sizes, int n_in,
                              void* d_out, int out_size) {
    const float*  x  = (const float*)d_in[0];
    const float4* W4 = (const float4*)d_in[1];
    const float4* b4 = (const float4*)d_in[2];
    float4* out4 = (float4*)d_out;

    dim3 grid(D_DIM, GRID_Y);   // 512 x 2 = 1024 blocks
    dense_embed_kernel<<<grid, 256>>>(x, W4, b4, out4);
}

// round 17
// speedup vs baseline: 1.0805x; 1.0805x over previous
#include <cuda_runtime.h>

// out[t,b,i,e] = x[t,b,i] * W[i,e] + b[e]
// T=8, B=64, D=512, E=256. k = t*B+b in [0,512).
// out4[(k*512 + i)*64 + e4] = x[k*512 + i] * W4[i*64 + e4] + b4[e4]
//
// R16: R13 plateau kernel (41.44us wall best) with __launch_bounds__(256, 6)
// to force 6 resident blocks/SM (48 warps, 75% occ vs measured 63.6%).
// R15 showed DRAM% tracks the number of concurrent store streams downward;
// this tests the upward direction. Memory pattern byte-identical to R13.

#define D_DIM 512
#define E4    64
#define K_CHUNKS 8
#define K_PER_CHUNK 64
#define KK 16

__global__ __launch_bounds__(256, 6) void dense_embed_kernel(
    const float* __restrict__ x,    // [512 * 512]
    const float4* __restrict__ W4,  // [512 * 64]
    const float4* __restrict__ b4,  // [64]
    float4* __restrict__ out4)      // [512 * 512 * 64]
{
    const unsigned i  = blockIdx.x;               // 0..511
    const unsigned e4 = threadIdx.x & (E4 - 1);   // 0..63
    const unsigned kg = threadIdx.x >> 6;         // 0..3
    const unsigned k0 = blockIdx.y * K_PER_CHUNK + kg * KK;

    // Per-thread invariants
    const float4 w  = __ldg(&W4[i * E4 + e4]);
    const float4 bb = __ldg(&b4[e4]);

    const float* xp = x + (size_t)k0 * D_DIM + i;
    float4* op = out4 + ((size_t)k0 * D_DIM + i) * E4 + e4;

    // Batch all 16 x loads up front — independent, fully overlapped.
    float xv[KK];
    #pragma unroll
    for (int kk = 0; kk < KK; kk++)
        xv[kk] = __ldg(&xp[(size_t)kk * D_DIM]);

    // Pure store stream: 16 back-to-back FMA4 + evict-first STG.128.
    #pragma unroll
    for (int kk = 0; kk < KK; kk++) {
        float4 o;
        o.x = fmaf(xv[kk], w.x, bb.x);
        o.y = fmaf(xv[kk], w.y, bb.y);
        o.z = fmaf(xv[kk], w.z, bb.z);
        o.w = fmaf(xv[kk], w.w, bb.w);
        __stcs(&op[(size_t)kk * D_DIM * E4], o);
    }
}

extern "C" void kernel_launch(void* const* d_in, const int* in_sizes, int n_in,
                              void* d_out, int out_size) {
    const float*  x  = (const float*)d_in[0];
    const float4* W4 = (const float4*)d_in[1];
    const float4* b4 = (const float4*)d_in[2];
    float4* out4 = (float4*)d_out;

    dim3 grid(D_DIM, K_CHUNKS);   // 512 x 8 = 4096 blocks
    dense_embed_kernel<<<grid, 256>>>(x, W4, b4, out4);
}